// round 3
// baseline (speedup 1.0000x reference)
#include <cuda_runtime.h>
#include <math.h>

#define D_MODEL 1024
#define D_INNER 2048
#define D_STATE 16
#define D_CONV  4
#define DT_RANK 64
#define N_LAYERS 4
#define BATCH 2
#define SEQ 1024
#define NTOK (BATCH*SEQ)          // 2048 tokens
#define XDBL_W (DT_RANK + 2*D_STATE)   // 96
#define LN_EPS 1e-5f

// ---------------- scratch (device globals; no allocations) ----------------
__device__ float g_xcur[NTOK*D_MODEL];      // residual stream
__device__ float g_xn  [NTOK*D_MODEL];      // layernorm output
__device__ float g_xz  [NTOK*2*D_INNER];    // in_proj output [xm | z]
__device__ float g_xm  [NTOK*D_INNER];      // conv+silu output
__device__ float g_xdbl[NTOK*XDBL_W];       // x_proj output [dt_lowrank | B | C]
__device__ float g_dt  [NTOK*D_INNER];      // softplus(dt_proj)
__device__ float g_y   [NTOK*D_INNER];      // scan output (gated)

// ---------------- layernorm ----------------
__inline__ __device__ float block_sum_256(float v, float* sh) {
    #pragma unroll
    for (int o = 16; o > 0; o >>= 1) v += __shfl_xor_sync(0xffffffffu, v, o);
    int w = threadIdx.x >> 5;
    if ((threadIdx.x & 31) == 0) sh[w] = v;
    __syncthreads();
    float r = 0.f;
    if (threadIdx.x < 8) {
        r = sh[threadIdx.x];
        #pragma unroll
        for (int o = 4; o > 0; o >>= 1) r += __shfl_xor_sync(0xffu, r, o);
        if (threadIdx.x == 0) sh[0] = r;
    }
    __syncthreads();
    r = sh[0];
    __syncthreads();
    return r;
}

__global__ void __launch_bounds__(256) ln_kernel(
    const float* __restrict__ in, float* __restrict__ out,
    const float* __restrict__ gamma, const float* __restrict__ beta)
{
    __shared__ float sh[8];
    int row = blockIdx.x;
    const float* x = in + (size_t)row * D_MODEL;
    float v[4];
    float s = 0.f;
    #pragma unroll
    for (int i = 0; i < 4; i++) { v[i] = x[threadIdx.x + i*256]; s += v[i]; }
    float mu = block_sum_256(s, sh) * (1.f / D_MODEL);
    float sq = 0.f;
    #pragma unroll
    for (int i = 0; i < 4; i++) { float d = v[i] - mu; sq += d*d; }
    float var = block_sum_256(sq, sh) * (1.f / D_MODEL);
    float inv = rsqrtf(var + LN_EPS);
    #pragma unroll
    for (int i = 0; i < 4; i++) {
        int c = threadIdx.x + i*256;
        out[(size_t)row * D_MODEL + c] = (v[i] - mu) * inv * gamma[c] + beta[c];
    }
}

// ---------------- generic NT GEMM: C[m,n] = sum_k A[m,k]*B[n,k] ----------------
// EPI: 0 = store; 1 = bias + softplus; 2 = add into C (residual, in-place)
#define BM 128
#define BN 128
#define BK 16
#define TM 8
#define TN 8

template<int EPI>
__global__ void __launch_bounds__(256) gemm_nt(
    const float* __restrict__ A, const float* __restrict__ B, float* __restrict__ C,
    int M, int N, int K, int lda, int ldb, int ldc,
    const float* __restrict__ bias)
{
    __shared__ float As[BK][BM+4];
    __shared__ float Bs[BK][BN+4];

    int bm = blockIdx.y * BM;
    int bn = blockIdx.x * BN;
    int tid = threadIdx.x;
    int tx = tid & 15;        // 0..15 -> N
    int ty = tid >> 4;        // 0..15 -> M

    int lr = tid >> 2;        // 0..63 load row
    int lc = (tid & 3) * 4;   // 0,4,8,12

    float acc[TM][TN];
    #pragma unroll
    for (int i = 0; i < TM; i++)
        #pragma unroll
        for (int j = 0; j < TN; j++) acc[i][j] = 0.f;

    for (int k0 = 0; k0 < K; k0 += BK) {
        #pragma unroll
        for (int h = 0; h < 2; h++) {
            int row = lr + h*64;
            float4 v = *(const float4*)(A + (size_t)(bm + row) * lda + k0 + lc);
            As[lc+0][row] = v.x; As[lc+1][row] = v.y;
            As[lc+2][row] = v.z; As[lc+3][row] = v.w;
        }
        #pragma unroll
        for (int h = 0; h < 2; h++) {
            int row = lr + h*64;
            float4 v = make_float4(0.f,0.f,0.f,0.f);
            if (bn + row < N)
                v = *(const float4*)(B + (size_t)(bn + row) * ldb + k0 + lc);
            Bs[lc+0][row] = v.x; Bs[lc+1][row] = v.y;
            Bs[lc+2][row] = v.z; Bs[lc+3][row] = v.w;
        }
        __syncthreads();
        #pragma unroll
        for (int k = 0; k < BK; k++) {
            float af[TM], bf[TN];
            #pragma unroll
            for (int i = 0; i < TM; i++) af[i] = As[k][ty*TM + i];
            #pragma unroll
            for (int j = 0; j < TN; j++) bf[j] = Bs[k][tx*TN + j];
            #pragma unroll
            for (int i = 0; i < TM; i++)
                #pragma unroll
                for (int j = 0; j < TN; j++)
                    acc[i][j] = fmaf(af[i], bf[j], acc[i][j]);
        }
        __syncthreads();
    }

    #pragma unroll
    for (int i = 0; i < TM; i++) {
        int m = bm + ty*TM + i;
        #pragma unroll
        for (int j = 0; j < TN; j++) {
            int n = bn + tx*TN + j;
            if (n < N) {
                size_t idx = (size_t)m * ldc + n;
                float v = acc[i][j];
                if (EPI == 1) {
                    v += bias[n];
                    v = (v > 20.f) ? v : log1pf(__expf(v));
                } else if (EPI == 2) {
                    v += C[idx];
                }
                C[idx] = v;
            }
        }
    }
}

// ---------------- causal depthwise conv + silu ----------------
__global__ void __launch_bounds__(256) conv_kernel(
    const float* __restrict__ xz, const float* __restrict__ cw,
    const float* __restrict__ cb, float* __restrict__ xm)
{
    int idx = blockIdx.x * 256 + threadIdx.x;       // over NTOK*D_INNER
    int d = idx & (D_INNER - 1);
    int t = idx >> 11;                               // token
    int l = t & (SEQ - 1);
    int base = t << 11;                              // t * D_INNER in xm terms
    float acc = cb[d];
    #pragma unroll
    for (int j = 0; j < D_CONV; j++) {
        int ll = l - (D_CONV - 1) + j;
        if (ll >= 0)
            acc = fmaf(cw[d*D_CONV + j],
                       xz[(size_t)(t - (D_CONV - 1) + j) * (2*D_INNER) + d], acc);
    }
    // silu
    float s = acc / (1.f + __expf(-acc));
    xm[(size_t)base + d] = s;
}

// ---------------- selective scan + skip + gate ----------------
// One thread per (channel, state). channel = b*D_INNER + d. 16 states per channel.
__global__ void __launch_bounds__(256) scan_kernel(
    const float* __restrict__ dt, const float* __restrict__ xdbl,
    const float* __restrict__ xm, const float* __restrict__ xz,
    const float* __restrict__ A_log, const float* __restrict__ D_skip,
    float* __restrict__ y)
{
    int g = blockIdx.x * 256 + threadIdx.x;
    int s  = g & (D_STATE - 1);
    int ch = g >> 4;
    int d = ch & (D_INNER - 1);
    int b = ch >> 11;

    float A = -__expf(A_log[d*D_STATE + s]);
    float Dv = D_skip[d];
    float h = 0.f;

    #pragma unroll 2
    for (int l = 0; l < SEQ; l++) {
        int t = b*SEQ + l;
        float dtv = dt[(size_t)t * D_INNER + d];
        float Bv  = xdbl[(size_t)t * XDBL_W + DT_RANK + s];
        float Cv  = xdbl[(size_t)t * XDBL_W + DT_RANK + D_STATE + s];
        float xv  = xm[(size_t)t * D_INNER + d];
        float dA  = __expf(dtv * A);
        h = fmaf(dA, h, dtv * Bv * xv);
        float p = h * Cv;
        #pragma unroll
        for (int o = 8; o > 0; o >>= 1) p += __shfl_xor_sync(0xffffffffu, p, o);
        if (s == 0) {
            float yv = p + xv * Dv;
            float zv = xz[(size_t)t * (2*D_INNER) + D_INNER + d];
            yv *= zv / (1.f + __expf(-zv));        // * silu(z)
            y[(size_t)t * D_INNER + d] = yv;
        }
    }
}

// ---------------- host launch ----------------
extern "C" void kernel_launch(void* const* d_in, const int* in_sizes, int n_in,
                              void* d_out, int out_size)
{
    const float* x          = (const float*)d_in[0];
    const float* in_proj_w  = (const float*)d_in[1];
    const float* conv_w     = (const float*)d_in[2];
    const float* conv_b     = (const float*)d_in[3];
    const float* x_proj_w   = (const float*)d_in[4];
    const float* dt_proj_w  = (const float*)d_in[5];
    const float* dt_proj_b  = (const float*)d_in[6];
    const float* A_log      = (const float*)d_in[7];
    const float* D_skip     = (const float*)d_in[8];
    const float* out_proj_w = (const float*)d_in[9];
    const float* ln_g       = (const float*)d_in[10];
    const float* ln_b       = (const float*)d_in[11];

    float *xcur, *xn, *xz, *xm, *xdbl, *dt, *y;
    cudaGetSymbolAddress((void**)&xcur, g_xcur);
    cudaGetSymbolAddress((void**)&xn,   g_xn);
    cudaGetSymbolAddress((void**)&xz,   g_xz);
    cudaGetSymbolAddress((void**)&xm,   g_xm);
    cudaGetSymbolAddress((void**)&xdbl, g_xdbl);
    cudaGetSymbolAddress((void**)&dt,   g_dt);
    cudaGetSymbolAddress((void**)&y,    g_y);

    cudaMemcpyAsync(xcur, x, sizeof(float)*NTOK*D_MODEL, cudaMemcpyDeviceToDevice);

    for (int l = 0; l < N_LAYERS; l++) {
        const float* W_in  = in_proj_w  + (size_t)l * 2*D_INNER * D_MODEL;
        const float* cw    = conv_w     + (size_t)l * D_INNER * D_CONV;
        const float* cb    = conv_b     + (size_t)l * D_INNER;
        const float* W_xp  = x_proj_w   + (size_t)l * XDBL_W * D_INNER;
        const float* W_dt  = dt_proj_w  + (size_t)l * D_INNER * DT_RANK;
        const float* b_dt  = dt_proj_b  + (size_t)l * D_INNER;
        const float* Al    = A_log      + (size_t)l * D_INNER * D_STATE;
        const float* Dl    = D_skip     + (size_t)l * D_INNER;
        const float* W_out = out_proj_w + (size_t)l * D_MODEL * D_INNER;

        ln_kernel<<<NTOK, 256>>>(xcur, xn, ln_g, ln_b);

        // in_proj: [2048,1024] x [4096,1024]^T -> [2048,4096]
        gemm_nt<0><<<dim3(2*D_INNER/BN, NTOK/BM), 256>>>(
            xn, W_in, xz, NTOK, 2*D_INNER, D_MODEL, D_MODEL, D_MODEL, 2*D_INNER, nullptr);

        conv_kernel<<<NTOK*D_INNER/256, 256>>>(xz, cw, cb, xm);

        // x_proj: [2048,2048] x [96,2048]^T -> [2048,96]
        gemm_nt<0><<<dim3(1, NTOK/BM), 256>>>(
            xm, W_xp, xdbl, NTOK, XDBL_W, D_INNER, D_INNER, D_INNER, XDBL_W, nullptr);

        // dt_proj + bias + softplus: [2048,64] x [2048,64]^T -> [2048,2048]
        gemm_nt<1><<<dim3(D_INNER/BN, NTOK/BM), 256>>>(
            xdbl, W_dt, dt, NTOK, D_INNER, DT_RANK, XDBL_W, DT_RANK, D_INNER, b_dt);

        scan_kernel<<<(BATCH*D_INNER*D_STATE)/256, 256>>>(dt, xdbl, xm, xz, Al, Dl, y);

        // out_proj + residual: [2048,2048] x [1024,2048]^T -> += xcur
        gemm_nt<2><<<dim3(D_MODEL/BN, NTOK/BM), 256>>>(
            y, W_out, xcur, NTOK, D_MODEL, D_INNER, D_INNER, D_INNER, D_MODEL, nullptr);
    }

    ln_kernel<<<NTOK, 256>>>(xcur, (float*)d_out, ln_g, ln_b);
}

// round 5
// speedup vs baseline: 1.8945x; 1.8945x over previous
#include <cuda_runtime.h>
#include <cuda_bf16.h>
#include <math.h>
#include <cstdint>

#define D_MODEL 1024
#define D_INNER 2048
#define D_STATE 16
#define D_CONV  4
#define DT_RANK 64
#define N_LAYERS 4
#define BATCH 2
#define SEQ 1024
#define NTOK (BATCH*SEQ)               // 2048 tokens
#define XDBL_W (DT_RANK + 2*D_STATE)   // 96
#define LN_EPS 1e-5f
#define XPS 8                           // x_proj K-splits

// ---------------- scratch (device globals; no allocations) ----------------
__device__ float g_xcur[NTOK*D_MODEL];
__device__ float g_xn  [NTOK*D_MODEL];
__device__ float g_xz  [NTOK*2*D_INNER];
__device__ float g_xm  [NTOK*D_INNER];
__device__ float g_xdbl[NTOK*XDBL_W];
__device__ float g_dt  [NTOK*D_INNER];
__device__ float g_y   [NTOK*D_INNER];
__device__ float g_xp_part[XPS*NTOK*XDBL_W];
// hi/lo bf16 operand buffers
__device__ __nv_bfloat16 g_ahi[NTOK*D_INNER];
__device__ __nv_bfloat16 g_alo[NTOK*D_INNER];
__device__ __nv_bfloat16 g_whi[2*D_INNER*D_MODEL];
__device__ __nv_bfloat16 g_wlo[2*D_INNER*D_MODEL];

// ================= bf16 mma.sync GEMM with hi/lo split =====================
// C[M, N] = A[M,K] * W[N,K]^T computed as Ahi*Whi + Ahi*Wlo + Alo*Whi.
// Tile: 128(M) x 128(N) x 32(K), 256 threads (8 warps in 2x4 grid).
// Each warp: 64x32 via m16n8k16 (4x4 subtiles). EPI: 0 store, 2 residual add.
#define AS_STRIDE 40   // bf16 elements per smem row (32 + 8 pad), 80B, 16B-aligned

template<int EPI>
__global__ void __launch_bounds__(256) mma_gemm(
    const __nv_bfloat16* __restrict__ Ahi, const __nv_bfloat16* __restrict__ Alo,
    const __nv_bfloat16* __restrict__ Whi, const __nv_bfloat16* __restrict__ Wlo,
    float* __restrict__ C, int N, int K, int ldc)
{
    __shared__ __nv_bfloat16 As[128*AS_STRIDE];
    __shared__ __nv_bfloat16 Bs[128*AS_STRIDE];

    int tid = threadIdx.x;
    int lane = tid & 31, wid = tid >> 5;
    int wm = wid >> 2, wn = wid & 3;      // warp 2x4
    int g  = lane >> 2, tg = lane & 3;    // mma lane decomposition
    int bm = blockIdx.y * 128;
    int bn = blockIdx.x * 128;

    int lrow  = tid >> 1;                 // 0..127 load row
    int lhalf = (tid & 1) * 16;           // 0 or 16 (bf16 elements)

    float acc[4][4][4];
    #pragma unroll
    for (int i = 0; i < 4; i++)
        #pragma unroll
        for (int j = 0; j < 4; j++)
            #pragma unroll
            for (int c = 0; c < 4; c++) acc[i][j][c] = 0.f;

    const int KT = K >> 5;        // k-tiles per segment
    const int NT = 3 * KT;

    uint4 pa0, pa1, pb0, pb1;

    // prefetch tile t into registers
    auto fetch = [&](int t) {
        int seg = (t < KT) ? 0 : ((t < 2*KT) ? 1 : 2);
        int kk = (t - seg*KT) << 5;
        const __nv_bfloat16* Ap = ((seg == 2) ? Alo : Ahi) + (size_t)(bm + lrow) * K + kk + lhalf;
        const __nv_bfloat16* Bp = ((seg == 1) ? Wlo : Whi) + (size_t)(bn + lrow) * K + kk + lhalf;
        pa0 = *(const uint4*)(Ap);
        pa1 = *(const uint4*)(Ap + 8);
        pb0 = *(const uint4*)(Bp);
        pb1 = *(const uint4*)(Bp + 8);
    };

    fetch(0);
    for (int t = 0; t < NT; t++) {
        // commit prefetched tile to smem
        *(uint4*)&As[lrow*AS_STRIDE + lhalf    ] = pa0;
        *(uint4*)&As[lrow*AS_STRIDE + lhalf + 8] = pa1;
        *(uint4*)&Bs[lrow*AS_STRIDE + lhalf    ] = pb0;
        *(uint4*)&Bs[lrow*AS_STRIDE + lhalf + 8] = pb1;
        __syncthreads();
        if (t + 1 < NT) fetch(t + 1);   // overlap next-tile global latency with mma

        #pragma unroll
        for (int ks = 0; ks < 32; ks += 16) {
            uint32_t af[4][4], bf[4][2];
            #pragma unroll
            for (int mi = 0; mi < 4; mi++) {
                int rb = wm*64 + mi*16;
                af[mi][0] = *(const uint32_t*)&As[(rb + g    )*AS_STRIDE + ks     + tg*2];
                af[mi][1] = *(const uint32_t*)&As[(rb + g + 8)*AS_STRIDE + ks     + tg*2];
                af[mi][2] = *(const uint32_t*)&As[(rb + g    )*AS_STRIDE + ks + 8 + tg*2];
                af[mi][3] = *(const uint32_t*)&As[(rb + g + 8)*AS_STRIDE + ks + 8 + tg*2];
            }
            #pragma unroll
            for (int ni = 0; ni < 4; ni++) {
                int cb = wn*32 + ni*8;
                bf[ni][0] = *(const uint32_t*)&Bs[(cb + g)*AS_STRIDE + ks     + tg*2];
                bf[ni][1] = *(const uint32_t*)&Bs[(cb + g)*AS_STRIDE + ks + 8 + tg*2];
            }
            #pragma unroll
            for (int mi = 0; mi < 4; mi++)
                #pragma unroll
                for (int ni = 0; ni < 4; ni++) {
                    asm volatile(
                        "mma.sync.aligned.m16n8k16.row.col.f32.bf16.bf16.f32 "
                        "{%0,%1,%2,%3}, {%4,%5,%6,%7}, {%8,%9}, {%0,%1,%2,%3};"
                        : "+f"(acc[mi][ni][0]), "+f"(acc[mi][ni][1]),
                          "+f"(acc[mi][ni][2]), "+f"(acc[mi][ni][3])
                        : "r"(af[mi][0]), "r"(af[mi][1]), "r"(af[mi][2]), "r"(af[mi][3]),
                          "r"(bf[ni][0]), "r"(bf[ni][1]));
                }
        }
        __syncthreads();
    }

    // epilogue: c0,c1 -> (row g, cols tg*2,tg*2+1); c2,c3 -> row g+8
    #pragma unroll
    for (int mi = 0; mi < 4; mi++) {
        int m0 = bm + wm*64 + mi*16 + g;
        #pragma unroll
        for (int ni = 0; ni < 4; ni++) {
            int n0 = bn + wn*32 + ni*8 + tg*2;
            float* d0 = C + (size_t)m0 * ldc + n0;
            float* d1 = C + (size_t)(m0 + 8) * ldc + n0;
            float v0 = acc[mi][ni][0], v1 = acc[mi][ni][1];
            float v2 = acc[mi][ni][2], v3 = acc[mi][ni][3];
            if (EPI == 2) { v0 += d0[0]; v1 += d0[1]; v2 += d1[0]; v3 += d1[1]; }
            d0[0] = v0; d0[1] = v1;
            d1[0] = v2; d1[1] = v3;
        }
    }
}

// ---------------- fp32 -> bf16 hi/lo split ----------------
__global__ void __launch_bounds__(256) cvt_hilo(
    const float* __restrict__ src, __nv_bfloat16* __restrict__ hi,
    __nv_bfloat16* __restrict__ lo, int n)
{
    int i = blockIdx.x * 256 + threadIdx.x;
    if (i < n) {
        float v = src[i];
        __nv_bfloat16 h = __float2bfloat16(v);
        float r = v - __bfloat162float(h);
        hi[i] = h;
        lo[i] = __float2bfloat16(r);
    }
}

// ---------------- layernorm ----------------
__inline__ __device__ float block_sum_256(float v, float* sh) {
    #pragma unroll
    for (int o = 16; o > 0; o >>= 1) v += __shfl_xor_sync(0xffffffffu, v, o);
    int w = threadIdx.x >> 5;
    if ((threadIdx.x & 31) == 0) sh[w] = v;
    __syncthreads();
    float r = 0.f;
    if (threadIdx.x < 8) {
        r = sh[threadIdx.x];
        #pragma unroll
        for (int o = 4; o > 0; o >>= 1) r += __shfl_xor_sync(0xffu, r, o);
        if (threadIdx.x == 0) sh[0] = r;
    }
    __syncthreads();
    r = sh[0];
    __syncthreads();
    return r;
}

__global__ void __launch_bounds__(256) ln_kernel(
    const float* __restrict__ in, float* __restrict__ out,
    const float* __restrict__ gamma, const float* __restrict__ beta)
{
    __shared__ float sh[8];
    int row = blockIdx.x;
    const float* x = in + (size_t)row * D_MODEL;
    float v[4];
    float s = 0.f;
    #pragma unroll
    for (int i = 0; i < 4; i++) { v[i] = x[threadIdx.x + i*256]; s += v[i]; }
    float mu = block_sum_256(s, sh) * (1.f / D_MODEL);
    float sq = 0.f;
    #pragma unroll
    for (int i = 0; i < 4; i++) { float d = v[i] - mu; sq += d*d; }
    float var = block_sum_256(sq, sh) * (1.f / D_MODEL);
    float inv = rsqrtf(var + LN_EPS);
    #pragma unroll
    for (int i = 0; i < 4; i++) {
        int c = threadIdx.x + i*256;
        out[(size_t)row * D_MODEL + c] = (v[i] - mu) * inv * gamma[c] + beta[c];
    }
}

// ---------------- SIMT GEMM (dt_proj only; small K) ----------------
#define BM 128
#define BN 128
#define BK 16

template<int EPI>
__global__ void __launch_bounds__(256) gemm_nt(
    const float* __restrict__ A, const float* __restrict__ B, float* __restrict__ C,
    int M, int N, int K, int lda, int ldb, int ldc,
    const float* __restrict__ bias)
{
    __shared__ float As[BK][BM+4];
    __shared__ float Bs[BK][BN+4];
    int bm = blockIdx.y * BM;
    int bn = blockIdx.x * BN;
    int tid = threadIdx.x;
    int tx = tid & 15;
    int ty = tid >> 4;
    int lr = tid >> 2;
    int lc = (tid & 3) * 4;

    float acc[8][8];
    #pragma unroll
    for (int i = 0; i < 8; i++)
        #pragma unroll
        for (int j = 0; j < 8; j++) acc[i][j] = 0.f;

    for (int k0 = 0; k0 < K; k0 += BK) {
        #pragma unroll
        for (int h = 0; h < 2; h++) {
            int row = lr + h*64;
            float4 v = *(const float4*)(A + (size_t)(bm + row) * lda + k0 + lc);
            As[lc+0][row] = v.x; As[lc+1][row] = v.y;
            As[lc+2][row] = v.z; As[lc+3][row] = v.w;
        }
        #pragma unroll
        for (int h = 0; h < 2; h++) {
            int row = lr + h*64;
            float4 v = make_float4(0.f,0.f,0.f,0.f);
            if (bn + row < N)
                v = *(const float4*)(B + (size_t)(bn + row) * ldb + k0 + lc);
            Bs[lc+0][row] = v.x; Bs[lc+1][row] = v.y;
            Bs[lc+2][row] = v.z; Bs[lc+3][row] = v.w;
        }
        __syncthreads();
        #pragma unroll
        for (int k = 0; k < BK; k++) {
            float af[8], bfr[8];
            #pragma unroll
            for (int i = 0; i < 8; i++) af[i] = As[k][ty*8 + i];
            #pragma unroll
            for (int j = 0; j < 8; j++) bfr[j] = Bs[k][tx*8 + j];
            #pragma unroll
            for (int i = 0; i < 8; i++)
                #pragma unroll
                for (int j = 0; j < 8; j++)
                    acc[i][j] = fmaf(af[i], bfr[j], acc[i][j]);
        }
        __syncthreads();
    }

    #pragma unroll
    for (int i = 0; i < 8; i++) {
        int m = bm + ty*8 + i;
        #pragma unroll
        for (int j = 0; j < 8; j++) {
            int n = bn + tx*8 + j;
            if (n < N) {
                size_t idx = (size_t)m * ldc + n;
                float v = acc[i][j];
                if (EPI == 1) {
                    v += bias[n];
                    v = (v > 20.f) ? v : log1pf(__expf(v));
                } else if (EPI == 2) {
                    v += C[idx];
                }
                C[idx] = v;
            }
        }
    }
}

// ---------------- x_proj split-K: [2048,96] = xm[2048,2048] x W[96,2048]^T --
__global__ void __launch_bounds__(256) gemm_xp(
    const float* __restrict__ A, const float* __restrict__ B,
    float* __restrict__ part)
{
    __shared__ float As[16][128+4];
    __shared__ float Bs[16][96+4];
    int bm = blockIdx.y * 128;
    int s = blockIdx.z;
    int kbase = s * (D_INNER / XPS);     // 256 per split
    int tid = threadIdx.x;
    int tx = tid & 15;                    // 6 cols each
    int ty = tid >> 4;                    // 8 rows each
    int lr = tid >> 2;
    int lc = (tid & 3) * 4;

    float acc[8][6];
    #pragma unroll
    for (int i = 0; i < 8; i++)
        #pragma unroll
        for (int j = 0; j < 6; j++) acc[i][j] = 0.f;

    for (int k0 = 0; k0 < D_INNER/XPS; k0 += 16) {
        #pragma unroll
        for (int h = 0; h < 2; h++) {
            int row = lr + h*64;
            float4 v = *(const float4*)(A + (size_t)(bm + row) * D_INNER + kbase + k0 + lc);
            As[lc+0][row] = v.x; As[lc+1][row] = v.y;
            As[lc+2][row] = v.z; As[lc+3][row] = v.w;
        }
        {
            int row = lr;
            if (row < 96) {
                float4 v = *(const float4*)(B + (size_t)row * D_INNER + kbase + k0 + lc);
                Bs[lc+0][row] = v.x; Bs[lc+1][row] = v.y;
                Bs[lc+2][row] = v.z; Bs[lc+3][row] = v.w;
            }
            int row2 = lr + 64;
            if (row2 < 96) {
                float4 v = *(const float4*)(B + (size_t)row2 * D_INNER + kbase + k0 + lc);
                Bs[lc+0][row2] = v.x; Bs[lc+1][row2] = v.y;
                Bs[lc+2][row2] = v.z; Bs[lc+3][row2] = v.w;
            }
        }
        __syncthreads();
        #pragma unroll
        for (int k = 0; k < 16; k++) {
            float af[8], bfr[6];
            #pragma unroll
            for (int i = 0; i < 8; i++) af[i] = As[k][ty*8 + i];
            #pragma unroll
            for (int j = 0; j < 6; j++) bfr[j] = Bs[k][tx*6 + j];
            #pragma unroll
            for (int i = 0; i < 8; i++)
                #pragma unroll
                for (int j = 0; j < 6; j++)
                    acc[i][j] = fmaf(af[i], bfr[j], acc[i][j]);
        }
        __syncthreads();
    }
    #pragma unroll
    for (int i = 0; i < 8; i++) {
        int m = bm + ty*8 + i;
        #pragma unroll
        for (int j = 0; j < 6; j++) {
            part[(size_t)s * NTOK * XDBL_W + (size_t)m * XDBL_W + tx*6 + j] = acc[i][j];
        }
    }
}

__global__ void __launch_bounds__(256) reduce_xp(
    const float* __restrict__ part, float* __restrict__ out)
{
    int i = blockIdx.x * 256 + threadIdx.x;
    if (i < NTOK * XDBL_W) {
        float s = 0.f;
        #pragma unroll
        for (int k = 0; k < XPS; k++) s += part[(size_t)k * NTOK * XDBL_W + i];
        out[i] = s;
    }
}

// ---------------- causal depthwise conv + silu ----------------
__global__ void __launch_bounds__(256) conv_kernel(
    const float* __restrict__ xz, const float* __restrict__ cw,
    const float* __restrict__ cb, float* __restrict__ xm)
{
    int idx = blockIdx.x * 256 + threadIdx.x;
    int d = idx & (D_INNER - 1);
    int t = idx >> 11;
    int l = t & (SEQ - 1);
    float acc = cb[d];
    #pragma unroll
    for (int j = 0; j < D_CONV; j++) {
        int ll = l - (D_CONV - 1) + j;
        if (ll >= 0)
            acc = fmaf(cw[d*D_CONV + j],
                       xz[(size_t)(t - (D_CONV - 1) + j) * (2*D_INNER) + d], acc);
    }
    float s = acc / (1.f + __expf(-acc));
    xm[(size_t)t * D_INNER + d] = s;
}

// ---------------- selective scan + skip + gate ----------------
__global__ void __launch_bounds__(256) scan_kernel(
    const float* __restrict__ dt, const float* __restrict__ xdbl,
    const float* __restrict__ xm, const float* __restrict__ xz,
    const float* __restrict__ A_log, const float* __restrict__ D_skip,
    float* __restrict__ y)
{
    int g = blockIdx.x * 256 + threadIdx.x;
    int s  = g & (D_STATE - 1);
    int ch = g >> 4;
    int d = ch & (D_INNER - 1);
    int b = ch >> 11;

    float A = -__expf(A_log[d*D_STATE + s]);
    float Dv = D_skip[d];
    float h = 0.f;

    #pragma unroll 2
    for (int l = 0; l < SEQ; l++) {
        int t = b*SEQ + l;
        float dtv = dt[(size_t)t * D_INNER + d];
        float Bv  = xdbl[(size_t)t * XDBL_W + DT_RANK + s];
        float Cv  = xdbl[(size_t)t * XDBL_W + DT_RANK + D_STATE + s];
        float xv  = xm[(size_t)t * D_INNER + d];
        float dA  = __expf(dtv * A);
        h = fmaf(dA, h, dtv * Bv * xv);
        float p = h * Cv;
        #pragma unroll
        for (int o = 8; o > 0; o >>= 1) p += __shfl_xor_sync(0xffffffffu, p, o);
        if (s == 0) {
            float yv = p + xv * Dv;
            float zv = xz[(size_t)t * (2*D_INNER) + D_INNER + d];
            yv *= zv / (1.f + __expf(-zv));
            y[(size_t)t * D_INNER + d] = yv;
        }
    }
}

// ---------------- host launch ----------------
extern "C" void kernel_launch(void* const* d_in, const int* in_sizes, int n_in,
                              void* d_out, int out_size)
{
    const float* x          = (const float*)d_in[0];
    const float* in_proj_w  = (const float*)d_in[1];
    const float* conv_w     = (const float*)d_in[2];
    const float* conv_b     = (const float*)d_in[3];
    const float* x_proj_w   = (const float*)d_in[4];
    const float* dt_proj_w  = (const float*)d_in[5];
    const float* dt_proj_b  = (const float*)d_in[6];
    const float* A_log      = (const float*)d_in[7];
    const float* D_skip     = (const float*)d_in[8];
    const float* out_proj_w = (const float*)d_in[9];
    const float* ln_g       = (const float*)d_in[10];
    const float* ln_b       = (const float*)d_in[11];

    float *xcur, *xn, *xz, *xm, *xdbl, *dt, *y, *xpp;
    __nv_bfloat16 *ahi, *alo, *whi, *wlo;
    cudaGetSymbolAddress((void**)&xcur, g_xcur);
    cudaGetSymbolAddress((void**)&xn,   g_xn);
    cudaGetSymbolAddress((void**)&xz,   g_xz);
    cudaGetSymbolAddress((void**)&xm,   g_xm);
    cudaGetSymbolAddress((void**)&xdbl, g_xdbl);
    cudaGetSymbolAddress((void**)&dt,   g_dt);
    cudaGetSymbolAddress((void**)&y,    g_y);
    cudaGetSymbolAddress((void**)&xpp,  g_xp_part);
    cudaGetSymbolAddress((void**)&ahi,  g_ahi);
    cudaGetSymbolAddress((void**)&alo,  g_alo);
    cudaGetSymbolAddress((void**)&whi,  g_whi);
    cudaGetSymbolAddress((void**)&wlo,  g_wlo);

    cudaMemcpyAsync(xcur, x, sizeof(float)*NTOK*D_MODEL, cudaMemcpyDeviceToDevice);

    for (int l = 0; l < N_LAYERS; l++) {
        const float* W_in  = in_proj_w  + (size_t)l * 2*D_INNER * D_MODEL;
        const float* cw    = conv_w     + (size_t)l * D_INNER * D_CONV;
        const float* cb    = conv_b     + (size_t)l * D_INNER;
        const float* W_xp  = x_proj_w   + (size_t)l * XDBL_W * D_INNER;
        const float* W_dt  = dt_proj_w  + (size_t)l * D_INNER * DT_RANK;
        const float* b_dt  = dt_proj_b  + (size_t)l * D_INNER;
        const float* Al    = A_log      + (size_t)l * D_INNER * D_STATE;
        const float* Dl    = D_skip     + (size_t)l * D_INNER;
        const float* W_out = out_proj_w + (size_t)l * D_MODEL * D_INNER;

        ln_kernel<<<NTOK, 256>>>(xcur, xn, ln_g, ln_b);

        // in_proj via mma.sync: [2048,1024] x [4096,1024]^T -> xz [2048,4096]
        cvt_hilo<<<(NTOK*D_MODEL)/256, 256>>>(xn, ahi, alo, NTOK*D_MODEL);
        cvt_hilo<<<(2*D_INNER*D_MODEL)/256, 256>>>(W_in, whi, wlo, 2*D_INNER*D_MODEL);
        mma_gemm<0><<<dim3(2*D_INNER/128, NTOK/128), 256>>>(
            ahi, alo, whi, wlo, xz, 2*D_INNER, D_MODEL, 2*D_INNER);

        conv_kernel<<<NTOK*D_INNER/256, 256>>>(xz, cw, cb, xm);

        // x_proj split-K + reduce -> xdbl [2048,96]
        gemm_xp<<<dim3(1, NTOK/128, XPS), 256>>>(xm, W_xp, xpp);
        reduce_xp<<<(NTOK*XDBL_W + 255)/256, 256>>>(xpp, xdbl);

        // dt_proj + bias + softplus: [2048,64] x [2048,64]^T -> dt [2048,2048]
        gemm_nt<1><<<dim3(D_INNER/BN, NTOK/BM), 256>>>(
            xdbl, W_dt, dt, NTOK, D_INNER, DT_RANK, XDBL_W, DT_RANK, D_INNER, b_dt);

        scan_kernel<<<(BATCH*D_INNER*D_STATE)/256, 256>>>(dt, xdbl, xm, xz, Al, Dl, y);

        // out_proj via mma.sync + residual: [2048,2048] x [1024,2048]^T -> += xcur
        cvt_hilo<<<(NTOK*D_INNER)/256, 256>>>(y, ahi, alo, NTOK*D_INNER);
        cvt_hilo<<<(D_MODEL*D_INNER)/256, 256>>>(W_out, whi, wlo, D_MODEL*D_INNER);
        mma_gemm<2><<<dim3(D_MODEL/128, NTOK/128), 256>>>(
            ahi, alo, whi, wlo, xcur, D_MODEL, D_INNER, D_MODEL);
    }

    ln_kernel<<<NTOK, 256>>>(xcur, (float*)d_out, ln_g, ln_b);
}

// round 6
// speedup vs baseline: 2.2141x; 1.1687x over previous
#include <cuda_runtime.h>
#include <cuda_bf16.h>
#include <math.h>
#include <cstdint>

#define D_MODEL 1024
#define D_INNER 2048
#define D_STATE 16
#define D_CONV  4
#define DT_RANK 64
#define N_LAYERS 4
#define BATCH 2
#define SEQ 1024
#define NTOK (BATCH*SEQ)               // 2048 tokens
#define XDBL_W (DT_RANK + 2*D_STATE)   // 96
#define LN_EPS 1e-5f
#define XPS 8                           // x_proj K-splits

// ---------------- scratch (device globals; no allocations) ----------------
__device__ float g_xcur[NTOK*D_MODEL];
__device__ float g_xn  [NTOK*D_MODEL];
__device__ float g_xz  [NTOK*2*D_INNER];
__device__ float g_xm  [NTOK*D_INNER];
__device__ float g_xdbl[NTOK*XDBL_W];
__device__ float g_dt  [NTOK*D_INNER];
__device__ float g_y   [NTOK*D_INNER];
__device__ float g_xp_part[XPS*NTOK*XDBL_W];
__device__ __nv_bfloat16 g_ahi[NTOK*D_INNER];
__device__ __nv_bfloat16 g_alo[NTOK*D_INNER];
__device__ __nv_bfloat16 g_whi[2*D_INNER*D_MODEL];
__device__ __nv_bfloat16 g_wlo[2*D_INNER*D_MODEL];

__device__ __forceinline__ uint32_t smem_u32(const void* p) {
    uint32_t a;
    asm("{ .reg .u64 t; cvta.to.shared.u64 t, %1; cvt.u32.u64 %0, t; }"
        : "=r"(a) : "l"(p));
    return a;
}

// ================= bf16 mma.sync GEMM with hi/lo split =====================
// C[M,N] = A[M,K]*W[N,K]^T as Ahi*Whi + Ahi*Wlo + Alo*Whi (fp32 accum).
// Tile: BMT(M) x 128(N) x 32(K). 256 threads = 8 warps (2 x 4).
// cp.async double-buffered stages holding all 4 tiles; ldmatrix fragments.
#define PITCH 40   // bf16 elements per smem row (stride 5 x 16B granules: conflict-free)

template<int BMT, int EPI>
__global__ void __launch_bounds__(256) mma_gemm(
    const __nv_bfloat16* __restrict__ Ahi, const __nv_bfloat16* __restrict__ Alo,
    const __nv_bfloat16* __restrict__ Whi, const __nv_bfloat16* __restrict__ Wlo,
    float* __restrict__ C, int K, int ldc)
{
    extern __shared__ __align__(16) __nv_bfloat16 smem[];
    constexpr int A_EL = BMT * PITCH;         // elements per A tile
    constexpr int W_EL = 128 * PITCH;         // elements per W tile
    constexpr int STAGE_EL = 2*A_EL + 2*W_EL;
    constexpr int STAGE_B  = STAGE_EL * 2;    // bytes
    constexpr int MI = BMT / 32;              // m16 subtiles per warp

    int tid = threadIdx.x;
    int lane = tid & 31, wid = tid >> 5;
    int wm = wid >> 2, wn = wid & 3;
    int g = lane >> 2, tg = lane & 3;
    int bm = blockIdx.y * BMT;
    int bn = blockIdx.x * 128;
    uint32_t sb = smem_u32(smem);

    float acc[MI][4][4];
    #pragma unroll
    for (int i = 0; i < MI; i++)
        #pragma unroll
        for (int j = 0; j < 4; j++)
            #pragma unroll
            for (int c = 0; c < 4; c++) acc[i][j][c] = 0.f;

    const int NC = K >> 5;
    constexpr int ACH = BMT * 4;              // 16B chunks per A tile
    constexpr int TOT = 2*ACH + 1024;         // + 2 W tiles (512 chunks each)

    // ---- async stage loader ----
    auto issue_stage = [&](int c) {
        int k0 = c << 5;
        uint32_t sbase = sb + (uint32_t)(c & 1) * STAGE_B;
        for (int ch = tid; ch < TOT; ch += 256) {
            const __nv_bfloat16* src;
            uint32_t dst;
            if (ch < ACH) {
                int r = ch >> 2, kg = ch & 3;
                src = Ahi + (size_t)(bm + r) * K + k0 + kg*8;
                dst = sbase + (uint32_t)(r*PITCH + kg*8) * 2;
            } else if (ch < 2*ACH) {
                int c2 = ch - ACH; int r = c2 >> 2, kg = c2 & 3;
                src = Alo + (size_t)(bm + r) * K + k0 + kg*8;
                dst = sbase + (uint32_t)(A_EL + r*PITCH + kg*8) * 2;
            } else if (ch < 2*ACH + 512) {
                int c2 = ch - 2*ACH; int r = c2 >> 2, kg = c2 & 3;
                src = Whi + (size_t)(bn + r) * K + k0 + kg*8;
                dst = sbase + (uint32_t)(2*A_EL + r*PITCH + kg*8) * 2;
            } else {
                int c2 = ch - 2*ACH - 512; int r = c2 >> 2, kg = c2 & 3;
                src = Wlo + (size_t)(bn + r) * K + k0 + kg*8;
                dst = sbase + (uint32_t)(2*A_EL + W_EL + r*PITCH + kg*8) * 2;
            }
            asm volatile("cp.async.ca.shared.global [%0], [%1], 16;"
                         :: "r"(dst), "l"(src));
        }
        asm volatile("cp.async.commit_group;" ::: "memory");
    };

    issue_stage(0);
    for (int c = 0; c < NC; c++) {
        if (c + 1 < NC) {
            issue_stage(c + 1);
            asm volatile("cp.async.wait_group 1;" ::: "memory");
        } else {
            asm volatile("cp.async.wait_group 0;" ::: "memory");
        }
        __syncthreads();

        uint32_t sbase = sb + (uint32_t)(c & 1) * STAGE_B;
        #pragma unroll
        for (int ks = 0; ks < 32; ks += 16) {
            // ---- A hi fragments (ldmatrix x4 per m16 subtile) ----
            uint32_t ah[MI][4];
            #pragma unroll
            for (int mi = 0; mi < MI; mi++) {
                int rb = wm * (BMT/2) + mi*16;
                int rl = rb + (lane & 15);
                int cl = ks + ((lane >> 4) << 3);
                uint32_t ad = sbase + (uint32_t)(rl*PITCH + cl) * 2;
                asm volatile("ldmatrix.sync.aligned.m8n8.x4.shared.b16 {%0,%1,%2,%3}, [%4];"
                    : "=r"(ah[mi][0]), "=r"(ah[mi][1]), "=r"(ah[mi][2]), "=r"(ah[mi][3])
                    : "r"(ad));
            }
            // ---- B hi & lo fragments (x4 covers two n8 tiles) ----
            uint32_t bh[4][2], bl[4][2];
            #pragma unroll
            for (int nj = 0; nj < 2; nj++) {
                int cb = wn*32 + nj*16;
                int rl = cb + (lane & 7) + ((lane & 16) ? 8 : 0);
                int cl = ks + (((lane >> 3) & 1) << 3);
                uint32_t off = (uint32_t)(rl*PITCH + cl) * 2;
                uint32_t adh = sbase + (uint32_t)(2*A_EL)*2 + off;
                uint32_t adl = adh + (uint32_t)W_EL*2;
                asm volatile("ldmatrix.sync.aligned.m8n8.x4.shared.b16 {%0,%1,%2,%3}, [%4];"
                    : "=r"(bh[2*nj][0]), "=r"(bh[2*nj][1]),
                      "=r"(bh[2*nj+1][0]), "=r"(bh[2*nj+1][1]) : "r"(adh));
                asm volatile("ldmatrix.sync.aligned.m8n8.x4.shared.b16 {%0,%1,%2,%3}, [%4];"
                    : "=r"(bl[2*nj][0]), "=r"(bl[2*nj][1]),
                      "=r"(bl[2*nj+1][0]), "=r"(bl[2*nj+1][1]) : "r"(adl));
            }
            #define MMA(ACC, AF, BF) \
                asm volatile( \
                    "mma.sync.aligned.m16n8k16.row.col.f32.bf16.bf16.f32 " \
                    "{%0,%1,%2,%3}, {%4,%5,%6,%7}, {%8,%9}, {%0,%1,%2,%3};" \
                    : "+f"((ACC)[0]), "+f"((ACC)[1]), "+f"((ACC)[2]), "+f"((ACC)[3]) \
                    : "r"((AF)[0]), "r"((AF)[1]), "r"((AF)[2]), "r"((AF)[3]), \
                      "r"((BF)[0]), "r"((BF)[1]))
            #pragma unroll
            for (int mi = 0; mi < MI; mi++)
                #pragma unroll
                for (int ni = 0; ni < 4; ni++) MMA(acc[mi][ni], ah[mi], bh[ni]);
            #pragma unroll
            for (int mi = 0; mi < MI; mi++)
                #pragma unroll
                for (int ni = 0; ni < 4; ni++) MMA(acc[mi][ni], ah[mi], bl[ni]);
            // ---- A lo fragments, third product ----
            uint32_t al2[MI][4];
            #pragma unroll
            for (int mi = 0; mi < MI; mi++) {
                int rb = wm * (BMT/2) + mi*16;
                int rl = rb + (lane & 15);
                int cl = ks + ((lane >> 4) << 3);
                uint32_t ad = sbase + (uint32_t)A_EL*2 + (uint32_t)(rl*PITCH + cl) * 2;
                asm volatile("ldmatrix.sync.aligned.m8n8.x4.shared.b16 {%0,%1,%2,%3}, [%4];"
                    : "=r"(al2[mi][0]), "=r"(al2[mi][1]), "=r"(al2[mi][2]), "=r"(al2[mi][3])
                    : "r"(ad));
            }
            #pragma unroll
            for (int mi = 0; mi < MI; mi++)
                #pragma unroll
                for (int ni = 0; ni < 4; ni++) MMA(acc[mi][ni], al2[mi], bh[ni]);
            #undef MMA
        }
        __syncthreads();
    }

    // ---- epilogue ----
    #pragma unroll
    for (int mi = 0; mi < MI; mi++) {
        int m0 = bm + wm*(BMT/2) + mi*16 + g;
        #pragma unroll
        for (int ni = 0; ni < 4; ni++) {
            int n0 = bn + wn*32 + ni*8 + tg*2;
            float* d0 = C + (size_t)m0 * ldc + n0;
            float* d1 = C + (size_t)(m0 + 8) * ldc + n0;
            float v0 = acc[mi][ni][0], v1 = acc[mi][ni][1];
            float v2 = acc[mi][ni][2], v3 = acc[mi][ni][3];
            if (EPI == 2) { v0 += d0[0]; v1 += d0[1]; v2 += d1[0]; v3 += d1[1]; }
            d0[0] = v0; d0[1] = v1;
            d1[0] = v2; d1[1] = v3;
        }
    }
}

// ---------------- fp32 -> bf16 hi/lo split ----------------
__global__ void __launch_bounds__(256) cvt_hilo(
    const float* __restrict__ src, __nv_bfloat16* __restrict__ hi,
    __nv_bfloat16* __restrict__ lo, int n)
{
    int i = blockIdx.x * 256 + threadIdx.x;
    if (i < n) {
        float v = src[i];
        __nv_bfloat16 h = __float2bfloat16(v);
        float r = v - __bfloat162float(h);
        hi[i] = h;
        lo[i] = __float2bfloat16(r);
    }
}

// ---------------- layernorm ----------------
__inline__ __device__ float block_sum_256(float v, float* sh) {
    #pragma unroll
    for (int o = 16; o > 0; o >>= 1) v += __shfl_xor_sync(0xffffffffu, v, o);
    int w = threadIdx.x >> 5;
    if ((threadIdx.x & 31) == 0) sh[w] = v;
    __syncthreads();
    float r = 0.f;
    if (threadIdx.x < 8) {
        r = sh[threadIdx.x];
        #pragma unroll
        for (int o = 4; o > 0; o >>= 1) r += __shfl_xor_sync(0xffu, r, o);
        if (threadIdx.x == 0) sh[0] = r;
    }
    __syncthreads();
    r = sh[0];
    __syncthreads();
    return r;
}

__global__ void __launch_bounds__(256) ln_kernel(
    const float* __restrict__ in, float* __restrict__ out,
    const float* __restrict__ gamma, const float* __restrict__ beta)
{
    __shared__ float sh[8];
    int row = blockIdx.x;
    const float* x = in + (size_t)row * D_MODEL;
    float v[4];
    float s = 0.f;
    #pragma unroll
    for (int i = 0; i < 4; i++) { v[i] = x[threadIdx.x + i*256]; s += v[i]; }
    float mu = block_sum_256(s, sh) * (1.f / D_MODEL);
    float sq = 0.f;
    #pragma unroll
    for (int i = 0; i < 4; i++) { float d = v[i] - mu; sq += d*d; }
    float var = block_sum_256(sq, sh) * (1.f / D_MODEL);
    float inv = rsqrtf(var + LN_EPS);
    #pragma unroll
    for (int i = 0; i < 4; i++) {
        int c = threadIdx.x + i*256;
        out[(size_t)row * D_MODEL + c] = (v[i] - mu) * inv * gamma[c] + beta[c];
    }
}

// ---------------- SIMT GEMM (dt_proj only; small K) ----------------
#define BM 128
#define BN 128
#define BK 16

template<int EPI>
__global__ void __launch_bounds__(256) gemm_nt(
    const float* __restrict__ A, const float* __restrict__ B, float* __restrict__ C,
    int M, int N, int K, int lda, int ldb, int ldc,
    const float* __restrict__ bias)
{
    __shared__ float As[BK][BM+4];
    __shared__ float Bs[BK][BN+4];
    int bm = blockIdx.y * BM;
    int bn = blockIdx.x * BN;
    int tid = threadIdx.x;
    int tx = tid & 15;
    int ty = tid >> 4;
    int lr = tid >> 2;
    int lc = (tid & 3) * 4;

    float acc[8][8];
    #pragma unroll
    for (int i = 0; i < 8; i++)
        #pragma unroll
        for (int j = 0; j < 8; j++) acc[i][j] = 0.f;

    for (int k0 = 0; k0 < K; k0 += BK) {
        #pragma unroll
        for (int h = 0; h < 2; h++) {
            int row = lr + h*64;
            float4 v = *(const float4*)(A + (size_t)(bm + row) * lda + k0 + lc);
            As[lc+0][row] = v.x; As[lc+1][row] = v.y;
            As[lc+2][row] = v.z; As[lc+3][row] = v.w;
        }
        #pragma unroll
        for (int h = 0; h < 2; h++) {
            int row = lr + h*64;
            float4 v = make_float4(0.f,0.f,0.f,0.f);
            if (bn + row < N)
                v = *(const float4*)(B + (size_t)(bn + row) * ldb + k0 + lc);
            Bs[lc+0][row] = v.x; Bs[lc+1][row] = v.y;
            Bs[lc+2][row] = v.z; Bs[lc+3][row] = v.w;
        }
        __syncthreads();
        #pragma unroll
        for (int k = 0; k < BK; k++) {
            float af[8], bfr[8];
            #pragma unroll
            for (int i = 0; i < 8; i++) af[i] = As[k][ty*8 + i];
            #pragma unroll
            for (int j = 0; j < 8; j++) bfr[j] = Bs[k][tx*8 + j];
            #pragma unroll
            for (int i = 0; i < 8; i++)
                #pragma unroll
                for (int j = 0; j < 8; j++)
                    acc[i][j] = fmaf(af[i], bfr[j], acc[i][j]);
        }
        __syncthreads();
    }

    #pragma unroll
    for (int i = 0; i < 8; i++) {
        int m = bm + ty*8 + i;
        #pragma unroll
        for (int j = 0; j < 8; j++) {
            int n = bn + tx*8 + j;
            if (n < N) {
                size_t idx = (size_t)m * ldc + n;
                float v = acc[i][j];
                if (EPI == 1) {
                    v += bias[n];
                    v = (v > 20.f) ? v : log1pf(__expf(v));
                } else if (EPI == 2) {
                    v += C[idx];
                }
                C[idx] = v;
            }
        }
    }
}

// ---------------- x_proj split-K: [2048,96] = xm[2048,2048] x W[96,2048]^T --
__global__ void __launch_bounds__(256) gemm_xp(
    const float* __restrict__ A, const float* __restrict__ B,
    float* __restrict__ part)
{
    __shared__ float As[16][128+4];
    __shared__ float Bs[16][96+4];
    int bm = blockIdx.y * 128;
    int s = blockIdx.z;
    int kbase = s * (D_INNER / XPS);
    int tid = threadIdx.x;
    int tx = tid & 15;
    int ty = tid >> 4;
    int lr = tid >> 2;
    int lc = (tid & 3) * 4;

    float acc[8][6];
    #pragma unroll
    for (int i = 0; i < 8; i++)
        #pragma unroll
        for (int j = 0; j < 6; j++) acc[i][j] = 0.f;

    for (int k0 = 0; k0 < D_INNER/XPS; k0 += 16) {
        #pragma unroll
        for (int h = 0; h < 2; h++) {
            int row = lr + h*64;
            float4 v = *(const float4*)(A + (size_t)(bm + row) * D_INNER + kbase + k0 + lc);
            As[lc+0][row] = v.x; As[lc+1][row] = v.y;
            As[lc+2][row] = v.z; As[lc+3][row] = v.w;
        }
        {
            int row = lr;
            if (row < 96) {
                float4 v = *(const float4*)(B + (size_t)row * D_INNER + kbase + k0 + lc);
                Bs[lc+0][row] = v.x; Bs[lc+1][row] = v.y;
                Bs[lc+2][row] = v.z; Bs[lc+3][row] = v.w;
            }
            int row2 = lr + 64;
            if (row2 < 96) {
                float4 v = *(const float4*)(B + (size_t)row2 * D_INNER + kbase + k0 + lc);
                Bs[lc+0][row2] = v.x; Bs[lc+1][row2] = v.y;
                Bs[lc+2][row2] = v.z; Bs[lc+3][row2] = v.w;
            }
        }
        __syncthreads();
        #pragma unroll
        for (int k = 0; k < 16; k++) {
            float af[8], bfr[6];
            #pragma unroll
            for (int i = 0; i < 8; i++) af[i] = As[k][ty*8 + i];
            #pragma unroll
            for (int j = 0; j < 6; j++) bfr[j] = Bs[k][tx*6 + j];
            #pragma unroll
            for (int i = 0; i < 8; i++)
                #pragma unroll
                for (int j = 0; j < 6; j++)
                    acc[i][j] = fmaf(af[i], bfr[j], acc[i][j]);
        }
        __syncthreads();
    }
    #pragma unroll
    for (int i = 0; i < 8; i++) {
        int m = bm + ty*8 + i;
        #pragma unroll
        for (int j = 0; j < 6; j++) {
            part[(size_t)s * NTOK * XDBL_W + (size_t)m * XDBL_W + tx*6 + j] = acc[i][j];
        }
    }
}

__global__ void __launch_bounds__(256) reduce_xp(
    const float* __restrict__ part, float* __restrict__ out)
{
    int i = blockIdx.x * 256 + threadIdx.x;
    if (i < NTOK * XDBL_W) {
        float s = 0.f;
        #pragma unroll
        for (int k = 0; k < XPS; k++) s += part[(size_t)k * NTOK * XDBL_W + i];
        out[i] = s;
    }
}

// ---------------- causal depthwise conv + silu ----------------
__global__ void __launch_bounds__(256) conv_kernel(
    const float* __restrict__ xz, const float* __restrict__ cw,
    const float* __restrict__ cb, float* __restrict__ xm)
{
    int idx = blockIdx.x * 256 + threadIdx.x;
    int d = idx & (D_INNER - 1);
    int t = idx >> 11;
    int l = t & (SEQ - 1);
    float acc = cb[d];
    #pragma unroll
    for (int j = 0; j < D_CONV; j++) {
        int ll = l - (D_CONV - 1) + j;
        if (ll >= 0)
            acc = fmaf(cw[d*D_CONV + j],
                       xz[(size_t)(t - (D_CONV - 1) + j) * (2*D_INNER) + d], acc);
    }
    float s = acc / (1.f + __expf(-acc));
    xm[(size_t)t * D_INNER + d] = s;
}

// ---------------- selective scan + skip + gate ----------------
__global__ void __launch_bounds__(256) scan_kernel(
    const float* __restrict__ dt, const float* __restrict__ xdbl,
    const float* __restrict__ xm, const float* __restrict__ xz,
    const float* __restrict__ A_log, const float* __restrict__ D_skip,
    float* __restrict__ y)
{
    int g = blockIdx.x * 256 + threadIdx.x;
    int s  = g & (D_STATE - 1);
    int ch = g >> 4;
    int d = ch & (D_INNER - 1);
    int b = ch >> 11;

    float A = -__expf(A_log[d*D_STATE + s]);
    float Dv = D_skip[d];
    float h = 0.f;

    #pragma unroll 2
    for (int l = 0; l < SEQ; l++) {
        int t = b*SEQ + l;
        float dtv = dt[(size_t)t * D_INNER + d];
        float Bv  = xdbl[(size_t)t * XDBL_W + DT_RANK + s];
        float Cv  = xdbl[(size_t)t * XDBL_W + DT_RANK + D_STATE + s];
        float xv  = xm[(size_t)t * D_INNER + d];
        float dA  = __expf(dtv * A);
        h = fmaf(dA, h, dtv * Bv * xv);
        float p = h * Cv;
        #pragma unroll
        for (int o = 8; o > 0; o >>= 1) p += __shfl_xor_sync(0xffffffffu, p, o);
        if (s == 0) {
            float yv = p + xv * Dv;
            float zv = xz[(size_t)t * (2*D_INNER) + D_INNER + d];
            yv *= zv / (1.f + __expf(-zv));
            y[(size_t)t * D_INNER + d] = yv;
        }
    }
}

// ---------------- host launch ----------------
extern "C" void kernel_launch(void* const* d_in, const int* in_sizes, int n_in,
                              void* d_out, int out_size)
{
    const float* x          = (const float*)d_in[0];
    const float* in_proj_w  = (const float*)d_in[1];
    const float* conv_w     = (const float*)d_in[2];
    const float* conv_b     = (const float*)d_in[3];
    const float* x_proj_w   = (const float*)d_in[4];
    const float* dt_proj_w  = (const float*)d_in[5];
    const float* dt_proj_b  = (const float*)d_in[6];
    const float* A_log      = (const float*)d_in[7];
    const float* D_skip     = (const float*)d_in[8];
    const float* out_proj_w = (const float*)d_in[9];
    const float* ln_g       = (const float*)d_in[10];
    const float* ln_b       = (const float*)d_in[11];

    float *xcur, *xn, *xz, *xm, *xdbl, *dt, *y, *xpp;
    __nv_bfloat16 *ahi, *alo, *whi, *wlo;
    cudaGetSymbolAddress((void**)&xcur, g_xcur);
    cudaGetSymbolAddress((void**)&xn,   g_xn);
    cudaGetSymbolAddress((void**)&xz,   g_xz);
    cudaGetSymbolAddress((void**)&xm,   g_xm);
    cudaGetSymbolAddress((void**)&xdbl, g_xdbl);
    cudaGetSymbolAddress((void**)&dt,   g_dt);
    cudaGetSymbolAddress((void**)&y,    g_y);
    cudaGetSymbolAddress((void**)&xpp,  g_xp_part);
    cudaGetSymbolAddress((void**)&ahi,  g_ahi);
    cudaGetSymbolAddress((void**)&alo,  g_alo);
    cudaGetSymbolAddress((void**)&whi,  g_whi);
    cudaGetSymbolAddress((void**)&wlo,  g_wlo);

    // dynamic smem: stage = (2*BMT + 2*128) * 40 * 2 bytes; two stages
    const int SMEM_128 = 2 * (2*128 + 2*128) * PITCH * 2;   // 81920
    const int SMEM_64  = 2 * (2*64  + 2*128) * PITCH * 2;   // 61440
    cudaFuncSetAttribute(mma_gemm<128,0>, cudaFuncAttributeMaxDynamicSharedMemorySize, SMEM_128);
    cudaFuncSetAttribute(mma_gemm<64,2>,  cudaFuncAttributeMaxDynamicSharedMemorySize, SMEM_64);

    cudaMemcpyAsync(xcur, x, sizeof(float)*NTOK*D_MODEL, cudaMemcpyDeviceToDevice);

    for (int l = 0; l < N_LAYERS; l++) {
        const float* W_in  = in_proj_w  + (size_t)l * 2*D_INNER * D_MODEL;
        const float* cw    = conv_w     + (size_t)l * D_INNER * D_CONV;
        const float* cb    = conv_b     + (size_t)l * D_INNER;
        const float* W_xp  = x_proj_w   + (size_t)l * XDBL_W * D_INNER;
        const float* W_dt  = dt_proj_w  + (size_t)l * D_INNER * DT_RANK;
        const float* b_dt  = dt_proj_b  + (size_t)l * D_INNER;
        const float* Al    = A_log      + (size_t)l * D_INNER * D_STATE;
        const float* Dl    = D_skip     + (size_t)l * D_INNER;
        const float* W_out = out_proj_w + (size_t)l * D_MODEL * D_INNER;

        ln_kernel<<<NTOK, 256>>>(xcur, xn, ln_g, ln_b);

        // in_proj: [2048,1024] x [4096,1024]^T -> xz [2048,4096]
        cvt_hilo<<<(NTOK*D_MODEL)/256, 256>>>(xn, ahi, alo, NTOK*D_MODEL);
        cvt_hilo<<<(2*D_INNER*D_MODEL)/256, 256>>>(W_in, whi, wlo, 2*D_INNER*D_MODEL);
        mma_gemm<128,0><<<dim3(2*D_INNER/128, NTOK/128), 256, SMEM_128>>>(
            ahi, alo, whi, wlo, xz, D_MODEL, 2*D_INNER);

        conv_kernel<<<NTOK*D_INNER/256, 256>>>(xz, cw, cb, xm);

        // x_proj split-K + reduce -> xdbl [2048,96]
        gemm_xp<<<dim3(1, NTOK/128, XPS), 256>>>(xm, W_xp, xpp);
        reduce_xp<<<(NTOK*XDBL_W + 255)/256, 256>>>(xpp, xdbl);

        // dt_proj + bias + softplus: [2048,64] x [2048,64]^T -> dt [2048,2048]
        gemm_nt<1><<<dim3(D_INNER/BN, NTOK/BM), 256>>>(
            xdbl, W_dt, dt, NTOK, D_INNER, DT_RANK, XDBL_W, DT_RANK, D_INNER, b_dt);

        scan_kernel<<<(BATCH*D_INNER*D_STATE)/256, 256>>>(dt, xdbl, xm, xz, Al, Dl, y);

        // out_proj + residual: [2048,2048] x [1024,2048]^T -> += xcur (tile 64x128)
        cvt_hilo<<<(NTOK*D_INNER)/256, 256>>>(y, ahi, alo, NTOK*D_INNER);
        cvt_hilo<<<(D_MODEL*D_INNER)/256, 256>>>(W_out, whi, wlo, D_MODEL*D_INNER);
        mma_gemm<64,2><<<dim3(D_MODEL/128, NTOK/64), 256, SMEM_64>>>(
            ahi, alo, whi, wlo, xcur, D_INNER, D_MODEL);
    }

    ln_kernel<<<NTOK, 256>>>(xcur, (float*)d_out, ln_g, ln_b);
}

// round 7
// speedup vs baseline: 4.2628x; 1.9253x over previous
#include <cuda_runtime.h>
#include <cuda_bf16.h>
#include <math.h>
#include <cstdint>

#define D_MODEL 1024
#define D_INNER 2048
#define D_STATE 16
#define D_CONV  4
#define DT_RANK 64
#define N_LAYERS 4
#define BATCH 2
#define SEQ 1024
#define NTOK (BATCH*SEQ)               // 2048 tokens
#define XDBL_W (DT_RANK + 2*D_STATE)   // 96
#define LN_EPS 1e-5f
#define XPS 8                           // x_proj K-splits

// ---------------- scratch (device globals; no allocations) ----------------
__device__ float g_xcur[NTOK*D_MODEL];
__device__ float g_xz  [NTOK*2*D_INNER];
__device__ float g_xm  [NTOK*D_INNER];
__device__ float g_xdbl[NTOK*XDBL_W];
__device__ float g_dt  [NTOK*D_INNER];
__device__ float g_xp_part[XPS*NTOK*XDBL_W];
__device__ __nv_bfloat16 g_ahi[NTOK*D_INNER];
__device__ __nv_bfloat16 g_alo[NTOK*D_INNER];
__device__ __nv_bfloat16 g_whi[2*D_INNER*D_MODEL];
__device__ __nv_bfloat16 g_wlo[2*D_INNER*D_MODEL];

__device__ __forceinline__ uint32_t smem_u32(const void* p) {
    uint32_t a;
    asm("{ .reg .u64 t; cvta.to.shared.u64 t, %1; cvt.u32.u64 %0, t; }"
        : "=r"(a) : "l"(p));
    return a;
}

// ================= bf16 mma.sync GEMM with hi/lo split =====================
// C[M,N] = A[M,K]*W[N,K]^T as Ahi*Whi + Ahi*Wlo + Alo*Whi (fp32 accum).
// Tile: BMT(M) x 128(N) x 32(K). 256 threads = 8 warps (2 x 4).
#define PITCH 40   // bf16 elements per smem row (stride 5 x 16B granules: conflict-free)

template<int BMT, int EPI>
__global__ void __launch_bounds__(256) mma_gemm(
    const __nv_bfloat16* __restrict__ Ahi, const __nv_bfloat16* __restrict__ Alo,
    const __nv_bfloat16* __restrict__ Whi, const __nv_bfloat16* __restrict__ Wlo,
    float* __restrict__ C, int K, int ldc)
{
    extern __shared__ __align__(16) __nv_bfloat16 smem[];
    constexpr int A_EL = BMT * PITCH;
    constexpr int W_EL = 128 * PITCH;
    constexpr int STAGE_EL = 2*A_EL + 2*W_EL;
    constexpr int STAGE_B  = STAGE_EL * 2;
    constexpr int MI = BMT / 32;

    int tid = threadIdx.x;
    int lane = tid & 31, wid = tid >> 5;
    int wm = wid >> 2, wn = wid & 3;
    int g = lane >> 2, tg = lane & 3;
    int bm = blockIdx.y * BMT;
    int bn = blockIdx.x * 128;
    uint32_t sb = smem_u32(smem);

    float acc[MI][4][4];
    #pragma unroll
    for (int i = 0; i < MI; i++)
        #pragma unroll
        for (int j = 0; j < 4; j++)
            #pragma unroll
            for (int c = 0; c < 4; c++) acc[i][j][c] = 0.f;

    const int NC = K >> 5;
    constexpr int ACH = BMT * 4;
    constexpr int TOT = 2*ACH + 1024;

    auto issue_stage = [&](int c) {
        int k0 = c << 5;
        uint32_t sbase = sb + (uint32_t)(c & 1) * STAGE_B;
        for (int ch = tid; ch < TOT; ch += 256) {
            const __nv_bfloat16* src;
            uint32_t dst;
            if (ch < ACH) {
                int r = ch >> 2, kg = ch & 3;
                src = Ahi + (size_t)(bm + r) * K + k0 + kg*8;
                dst = sbase + (uint32_t)(r*PITCH + kg*8) * 2;
            } else if (ch < 2*ACH) {
                int c2 = ch - ACH; int r = c2 >> 2, kg = c2 & 3;
                src = Alo + (size_t)(bm + r) * K + k0 + kg*8;
                dst = sbase + (uint32_t)(A_EL + r*PITCH + kg*8) * 2;
            } else if (ch < 2*ACH + 512) {
                int c2 = ch - 2*ACH; int r = c2 >> 2, kg = c2 & 3;
                src = Whi + (size_t)(bn + r) * K + k0 + kg*8;
                dst = sbase + (uint32_t)(2*A_EL + r*PITCH + kg*8) * 2;
            } else {
                int c2 = ch - 2*ACH - 512; int r = c2 >> 2, kg = c2 & 3;
                src = Wlo + (size_t)(bn + r) * K + k0 + kg*8;
                dst = sbase + (uint32_t)(2*A_EL + W_EL + r*PITCH + kg*8) * 2;
            }
            asm volatile("cp.async.cg.shared.global [%0], [%1], 16;"
                         :: "r"(dst), "l"(src));
        }
        asm volatile("cp.async.commit_group;" ::: "memory");
    };

    issue_stage(0);
    for (int c = 0; c < NC; c++) {
        if (c + 1 < NC) {
            issue_stage(c + 1);
            asm volatile("cp.async.wait_group 1;" ::: "memory");
        } else {
            asm volatile("cp.async.wait_group 0;" ::: "memory");
        }
        __syncthreads();

        uint32_t sbase = sb + (uint32_t)(c & 1) * STAGE_B;
        #pragma unroll
        for (int ks = 0; ks < 32; ks += 16) {
            uint32_t ah[MI][4];
            #pragma unroll
            for (int mi = 0; mi < MI; mi++) {
                int rb = wm * (BMT/2) + mi*16;
                int rl = rb + (lane & 15);
                int cl = ks + ((lane >> 4) << 3);
                uint32_t ad = sbase + (uint32_t)(rl*PITCH + cl) * 2;
                asm volatile("ldmatrix.sync.aligned.m8n8.x4.shared.b16 {%0,%1,%2,%3}, [%4];"
                    : "=r"(ah[mi][0]), "=r"(ah[mi][1]), "=r"(ah[mi][2]), "=r"(ah[mi][3])
                    : "r"(ad));
            }
            uint32_t bh[4][2], bl[4][2];
            #pragma unroll
            for (int nj = 0; nj < 2; nj++) {
                int cb = wn*32 + nj*16;
                int rl = cb + (lane & 7) + ((lane & 16) ? 8 : 0);
                int cl = ks + (((lane >> 3) & 1) << 3);
                uint32_t off = (uint32_t)(rl*PITCH + cl) * 2;
                uint32_t adh = sbase + (uint32_t)(2*A_EL)*2 + off;
                uint32_t adl = adh + (uint32_t)W_EL*2;
                asm volatile("ldmatrix.sync.aligned.m8n8.x4.shared.b16 {%0,%1,%2,%3}, [%4];"
                    : "=r"(bh[2*nj][0]), "=r"(bh[2*nj][1]),
                      "=r"(bh[2*nj+1][0]), "=r"(bh[2*nj+1][1]) : "r"(adh));
                asm volatile("ldmatrix.sync.aligned.m8n8.x4.shared.b16 {%0,%1,%2,%3}, [%4];"
                    : "=r"(bl[2*nj][0]), "=r"(bl[2*nj][1]),
                      "=r"(bl[2*nj+1][0]), "=r"(bl[2*nj+1][1]) : "r"(adl));
            }
            #define MMA(ACC, AF, BF) \
                asm volatile( \
                    "mma.sync.aligned.m16n8k16.row.col.f32.bf16.bf16.f32 " \
                    "{%0,%1,%2,%3}, {%4,%5,%6,%7}, {%8,%9}, {%0,%1,%2,%3};" \
                    : "+f"((ACC)[0]), "+f"((ACC)[1]), "+f"((ACC)[2]), "+f"((ACC)[3]) \
                    : "r"((AF)[0]), "r"((AF)[1]), "r"((AF)[2]), "r"((AF)[3]), \
                      "r"((BF)[0]), "r"((BF)[1]))
            #pragma unroll
            for (int mi = 0; mi < MI; mi++)
                #pragma unroll
                for (int ni = 0; ni < 4; ni++) MMA(acc[mi][ni], ah[mi], bh[ni]);
            #pragma unroll
            for (int mi = 0; mi < MI; mi++)
                #pragma unroll
                for (int ni = 0; ni < 4; ni++) MMA(acc[mi][ni], ah[mi], bl[ni]);
            uint32_t al2[MI][4];
            #pragma unroll
            for (int mi = 0; mi < MI; mi++) {
                int rb = wm * (BMT/2) + mi*16;
                int rl = rb + (lane & 15);
                int cl = ks + ((lane >> 4) << 3);
                uint32_t ad = sbase + (uint32_t)A_EL*2 + (uint32_t)(rl*PITCH + cl) * 2;
                asm volatile("ldmatrix.sync.aligned.m8n8.x4.shared.b16 {%0,%1,%2,%3}, [%4];"
                    : "=r"(al2[mi][0]), "=r"(al2[mi][1]), "=r"(al2[mi][2]), "=r"(al2[mi][3])
                    : "r"(ad));
            }
            #pragma unroll
            for (int mi = 0; mi < MI; mi++)
                #pragma unroll
                for (int ni = 0; ni < 4; ni++) MMA(acc[mi][ni], al2[mi], bh[ni]);
            #undef MMA
        }
        __syncthreads();
    }

    #pragma unroll
    for (int mi = 0; mi < MI; mi++) {
        int m0 = bm + wm*(BMT/2) + mi*16 + g;
        #pragma unroll
        for (int ni = 0; ni < 4; ni++) {
            int n0 = bn + wn*32 + ni*8 + tg*2;
            float* d0 = C + (size_t)m0 * ldc + n0;
            float* d1 = C + (size_t)(m0 + 8) * ldc + n0;
            float v0 = acc[mi][ni][0], v1 = acc[mi][ni][1];
            float v2 = acc[mi][ni][2], v3 = acc[mi][ni][3];
            if (EPI == 2) { v0 += d0[0]; v1 += d0[1]; v2 += d1[0]; v3 += d1[1]; }
            d0[0] = v0; d0[1] = v1;
            d1[0] = v2; d1[1] = v3;
        }
    }
}

// ---------------- fp32 -> bf16 hi/lo split (weights) ----------------
__global__ void __launch_bounds__(256) cvt_hilo(
    const float* __restrict__ src, __nv_bfloat16* __restrict__ hi,
    __nv_bfloat16* __restrict__ lo, int n)
{
    int i = blockIdx.x * 256 + threadIdx.x;
    if (i < n) {
        float v = src[i];
        __nv_bfloat16 h = __float2bfloat16(v);
        float r = v - __bfloat162float(h);
        hi[i] = h;
        lo[i] = __float2bfloat16(r);
    }
}

// ---------------- layernorm (optionally emits bf16 hi/lo) ----------------
__inline__ __device__ float block_sum_256(float v, float* sh) {
    #pragma unroll
    for (int o = 16; o > 0; o >>= 1) v += __shfl_xor_sync(0xffffffffu, v, o);
    int w = threadIdx.x >> 5;
    if ((threadIdx.x & 31) == 0) sh[w] = v;
    __syncthreads();
    float r = 0.f;
    if (threadIdx.x < 8) {
        r = sh[threadIdx.x];
        #pragma unroll
        for (int o = 4; o > 0; o >>= 1) r += __shfl_xor_sync(0xffu, r, o);
        if (threadIdx.x == 0) sh[0] = r;
    }
    __syncthreads();
    r = sh[0];
    __syncthreads();
    return r;
}

__global__ void __launch_bounds__(256) ln_kernel(
    const float* __restrict__ in, float* __restrict__ out,
    __nv_bfloat16* __restrict__ hi, __nv_bfloat16* __restrict__ lo,
    const float* __restrict__ gamma, const float* __restrict__ beta)
{
    __shared__ float sh[8];
    int row = blockIdx.x;
    const float* x = in + (size_t)row * D_MODEL;
    float v[4];
    float s = 0.f;
    #pragma unroll
    for (int i = 0; i < 4; i++) { v[i] = x[threadIdx.x + i*256]; s += v[i]; }
    float mu = block_sum_256(s, sh) * (1.f / D_MODEL);
    float sq = 0.f;
    #pragma unroll
    for (int i = 0; i < 4; i++) { float d = v[i] - mu; sq += d*d; }
    float var = block_sum_256(sq, sh) * (1.f / D_MODEL);
    float inv = rsqrtf(var + LN_EPS);
    #pragma unroll
    for (int i = 0; i < 4; i++) {
        int c = threadIdx.x + i*256;
        float o = (v[i] - mu) * inv * gamma[c] + beta[c];
        size_t idx = (size_t)row * D_MODEL + c;
        if (out) out[idx] = o;
        if (hi) {
            __nv_bfloat16 h = __float2bfloat16(o);
            hi[idx] = h;
            lo[idx] = __float2bfloat16(o - __bfloat162float(h));
        }
    }
}

// ---------------- SIMT GEMM (dt_proj only; small K) ----------------
#define BM 128
#define BN 128
#define BK 16

template<int EPI>
__global__ void __launch_bounds__(256) gemm_nt(
    const float* __restrict__ A, const float* __restrict__ B, float* __restrict__ C,
    int M, int N, int K, int lda, int ldb, int ldc,
    const float* __restrict__ bias)
{
    __shared__ float As[BK][BM+4];
    __shared__ float Bs[BK][BN+4];
    int bm = blockIdx.y * BM;
    int bn = blockIdx.x * BN;
    int tid = threadIdx.x;
    int tx = tid & 15;
    int ty = tid >> 4;
    int lr = tid >> 2;
    int lc = (tid & 3) * 4;

    float acc[8][8];
    #pragma unroll
    for (int i = 0; i < 8; i++)
        #pragma unroll
        for (int j = 0; j < 8; j++) acc[i][j] = 0.f;

    for (int k0 = 0; k0 < K; k0 += BK) {
        #pragma unroll
        for (int h = 0; h < 2; h++) {
            int row = lr + h*64;
            float4 v = *(const float4*)(A + (size_t)(bm + row) * lda + k0 + lc);
            As[lc+0][row] = v.x; As[lc+1][row] = v.y;
            As[lc+2][row] = v.z; As[lc+3][row] = v.w;
        }
        #pragma unroll
        for (int h = 0; h < 2; h++) {
            int row = lr + h*64;
            float4 v = make_float4(0.f,0.f,0.f,0.f);
            if (bn + row < N)
                v = *(const float4*)(B + (size_t)(bn + row) * ldb + k0 + lc);
            Bs[lc+0][row] = v.x; Bs[lc+1][row] = v.y;
            Bs[lc+2][row] = v.z; Bs[lc+3][row] = v.w;
        }
        __syncthreads();
        #pragma unroll
        for (int k = 0; k < BK; k++) {
            float af[8], bfr[8];
            #pragma unroll
            for (int i = 0; i < 8; i++) af[i] = As[k][ty*8 + i];
            #pragma unroll
            for (int j = 0; j < 8; j++) bfr[j] = Bs[k][tx*8 + j];
            #pragma unroll
            for (int i = 0; i < 8; i++)
                #pragma unroll
                for (int j = 0; j < 8; j++)
                    acc[i][j] = fmaf(af[i], bfr[j], acc[i][j]);
        }
        __syncthreads();
    }

    #pragma unroll
    for (int i = 0; i < 8; i++) {
        int m = bm + ty*8 + i;
        #pragma unroll
        for (int j = 0; j < 8; j++) {
            int n = bn + tx*8 + j;
            if (n < N) {
                size_t idx = (size_t)m * ldc + n;
                float v = acc[i][j];
                if (EPI == 1) {
                    v += bias[n];
                    v = (v > 20.f) ? v : log1pf(__expf(v));
                } else if (EPI == 2) {
                    v += C[idx];
                }
                C[idx] = v;
            }
        }
    }
}

// ---------------- x_proj split-K ----------------
__global__ void __launch_bounds__(256) gemm_xp(
    const float* __restrict__ A, const float* __restrict__ B,
    float* __restrict__ part)
{
    __shared__ float As[16][128+4];
    __shared__ float Bs[16][96+4];
    int bm = blockIdx.y * 128;
    int s = blockIdx.z;
    int kbase = s * (D_INNER / XPS);
    int tid = threadIdx.x;
    int tx = tid & 15;
    int ty = tid >> 4;
    int lr = tid >> 2;
    int lc = (tid & 3) * 4;

    float acc[8][6];
    #pragma unroll
    for (int i = 0; i < 8; i++)
        #pragma unroll
        for (int j = 0; j < 6; j++) acc[i][j] = 0.f;

    for (int k0 = 0; k0 < D_INNER/XPS; k0 += 16) {
        #pragma unroll
        for (int h = 0; h < 2; h++) {
            int row = lr + h*64;
            float4 v = *(const float4*)(A + (size_t)(bm + row) * D_INNER + kbase + k0 + lc);
            As[lc+0][row] = v.x; As[lc+1][row] = v.y;
            As[lc+2][row] = v.z; As[lc+3][row] = v.w;
        }
        {
            int row = lr;
            if (row < 96) {
                float4 v = *(const float4*)(B + (size_t)row * D_INNER + kbase + k0 + lc);
                Bs[lc+0][row] = v.x; Bs[lc+1][row] = v.y;
                Bs[lc+2][row] = v.z; Bs[lc+3][row] = v.w;
            }
            int row2 = lr + 64;
            if (row2 < 96) {
                float4 v = *(const float4*)(B + (size_t)row2 * D_INNER + kbase + k0 + lc);
                Bs[lc+0][row2] = v.x; Bs[lc+1][row2] = v.y;
                Bs[lc+2][row2] = v.z; Bs[lc+3][row2] = v.w;
            }
        }
        __syncthreads();
        #pragma unroll
        for (int k = 0; k < 16; k++) {
            float af[8], bfr[6];
            #pragma unroll
            for (int i = 0; i < 8; i++) af[i] = As[k][ty*8 + i];
            #pragma unroll
            for (int j = 0; j < 6; j++) bfr[j] = Bs[k][tx*6 + j];
            #pragma unroll
            for (int i = 0; i < 8; i++)
                #pragma unroll
                for (int j = 0; j < 6; j++)
                    acc[i][j] = fmaf(af[i], bfr[j], acc[i][j]);
        }
        __syncthreads();
    }
    #pragma unroll
    for (int i = 0; i < 8; i++) {
        int m = bm + ty*8 + i;
        #pragma unroll
        for (int j = 0; j < 6; j++) {
            part[(size_t)s * NTOK * XDBL_W + (size_t)m * XDBL_W + tx*6 + j] = acc[i][j];
        }
    }
}

__global__ void __launch_bounds__(256) reduce_xp(
    const float* __restrict__ part, float* __restrict__ out)
{
    int i = blockIdx.x * 256 + threadIdx.x;
    if (i < NTOK * XDBL_W) {
        float s = 0.f;
        #pragma unroll
        for (int k = 0; k < XPS; k++) s += part[(size_t)k * NTOK * XDBL_W + i];
        out[i] = s;
    }
}

// ---------------- causal depthwise conv + silu ----------------
__global__ void __launch_bounds__(256) conv_kernel(
    const float* __restrict__ xz, const float* __restrict__ cw,
    const float* __restrict__ cb, float* __restrict__ xm)
{
    int idx = blockIdx.x * 256 + threadIdx.x;
    int d = idx & (D_INNER - 1);
    int t = idx >> 11;
    int l = t & (SEQ - 1);
    float acc = cb[d];
    #pragma unroll
    for (int j = 0; j < D_CONV; j++) {
        int ll = l - (D_CONV - 1) + j;
        if (ll >= 0)
            acc = fmaf(cw[d*D_CONV + j],
                       xz[(size_t)(t - (D_CONV - 1) + j) * (2*D_INNER) + d], acc);
    }
    float s = acc / (1.f + __expf(-acc));
    xm[(size_t)t * D_INNER + d] = s;
}

// ---------------- selective scan (register-buffered, MLP) ----------------
// Thread per (channel, state). Emits y as bf16 hi/lo (out_proj A operand).
#define TBUF 16
__global__ void __launch_bounds__(256) scan_kernel(
    const float* __restrict__ dt, const float* __restrict__ xdbl,
    const float* __restrict__ xm, const float* __restrict__ xz,
    const float* __restrict__ A_log, const float* __restrict__ D_skip,
    __nv_bfloat16* __restrict__ yhi, __nv_bfloat16* __restrict__ ylo)
{
    int gidx = blockIdx.x * 256 + threadIdx.x;
    int s  = gidx & (D_STATE - 1);
    int ch = gidx >> 4;
    int d = ch & (D_INNER - 1);
    int b = ch >> 11;

    float A = -__expf(A_log[d*D_STATE + s]);
    float Dv = D_skip[d];
    float h = 0.f;

    for (int t0 = 0; t0 < SEQ; t0 += TBUF) {
        float bd[TBUF], bx[TBUF], bB[TBUF], bC[TBUF], bz[TBUF];
        #pragma unroll
        for (int j = 0; j < TBUF; j++) {
            size_t t = (size_t)(b*SEQ + t0 + j);
            bd[j] = dt[t * D_INNER + d];
            bx[j] = xm[t * D_INNER + d];
            bB[j] = xdbl[t * XDBL_W + DT_RANK + s];
            bC[j] = xdbl[t * XDBL_W + DT_RANK + D_STATE + s];
            bz[j] = xz[t * (2*D_INNER) + D_INNER + d];
        }
        #pragma unroll
        for (int j = 0; j < TBUF; j++) {
            float dA = __expf(bd[j] * A);
            h = fmaf(dA, h, bd[j] * bB[j] * bx[j]);
            float p = h * bC[j];
            #pragma unroll
            for (int o = 8; o > 0; o >>= 1) p += __shfl_xor_sync(0xffffffffu, p, o);
            if (s == 0) {
                float yv = p + bx[j] * Dv;
                float zv = bz[j];
                yv *= zv / (1.f + __expf(-zv));
                size_t idx = (size_t)(b*SEQ + t0 + j) * D_INNER + d;
                __nv_bfloat16 hh = __float2bfloat16(yv);
                yhi[idx] = hh;
                ylo[idx] = __float2bfloat16(yv - __bfloat162float(hh));
            }
        }
    }
}

// ---------------- host launch ----------------
extern "C" void kernel_launch(void* const* d_in, const int* in_sizes, int n_in,
                              void* d_out, int out_size)
{
    const float* x          = (const float*)d_in[0];
    const float* in_proj_w  = (const float*)d_in[1];
    const float* conv_w     = (const float*)d_in[2];
    const float* conv_b     = (const float*)d_in[3];
    const float* x_proj_w   = (const float*)d_in[4];
    const float* dt_proj_w  = (const float*)d_in[5];
    const float* dt_proj_b  = (const float*)d_in[6];
    const float* A_log      = (const float*)d_in[7];
    const float* D_skip     = (const float*)d_in[8];
    const float* out_proj_w = (const float*)d_in[9];
    const float* ln_g       = (const float*)d_in[10];
    const float* ln_b       = (const float*)d_in[11];

    float *xcur, *xz, *xm, *xdbl, *dt, *xpp;
    __nv_bfloat16 *ahi, *alo, *whi, *wlo;
    cudaGetSymbolAddress((void**)&xcur, g_xcur);
    cudaGetSymbolAddress((void**)&xz,   g_xz);
    cudaGetSymbolAddress((void**)&xm,   g_xm);
    cudaGetSymbolAddress((void**)&xdbl, g_xdbl);
    cudaGetSymbolAddress((void**)&dt,   g_dt);
    cudaGetSymbolAddress((void**)&xpp,  g_xp_part);
    cudaGetSymbolAddress((void**)&ahi,  g_ahi);
    cudaGetSymbolAddress((void**)&alo,  g_alo);
    cudaGetSymbolAddress((void**)&whi,  g_whi);
    cudaGetSymbolAddress((void**)&wlo,  g_wlo);

    const int SMEM_128 = 2 * (2*128 + 2*128) * PITCH * 2;   // 81920
    const int SMEM_64  = 2 * (2*64  + 2*128) * PITCH * 2;   // 61440
    cudaFuncSetAttribute(mma_gemm<128,0>, cudaFuncAttributeMaxDynamicSharedMemorySize, SMEM_128);
    cudaFuncSetAttribute(mma_gemm<64,2>,  cudaFuncAttributeMaxDynamicSharedMemorySize, SMEM_64);

    cudaMemcpyAsync(xcur, x, sizeof(float)*NTOK*D_MODEL, cudaMemcpyDeviceToDevice);

    for (int l = 0; l < N_LAYERS; l++) {
        const float* W_in  = in_proj_w  + (size_t)l * 2*D_INNER * D_MODEL;
        const float* cw    = conv_w     + (size_t)l * D_INNER * D_CONV;
        const float* cb    = conv_b     + (size_t)l * D_INNER;
        const float* W_xp  = x_proj_w   + (size_t)l * XDBL_W * D_INNER;
        const float* W_dt  = dt_proj_w  + (size_t)l * D_INNER * DT_RANK;
        const float* b_dt  = dt_proj_b  + (size_t)l * D_INNER;
        const float* Al    = A_log      + (size_t)l * D_INNER * D_STATE;
        const float* Dl    = D_skip     + (size_t)l * D_INNER;
        const float* W_out = out_proj_w + (size_t)l * D_MODEL * D_INNER;

        // LN -> bf16 hi/lo directly (in_proj A operand)
        ln_kernel<<<NTOK, 256>>>(xcur, nullptr, ahi, alo, ln_g, ln_b);

        // in_proj: [2048,1024] x [4096,1024]^T -> xz [2048,4096]
        cvt_hilo<<<(2*D_INNER*D_MODEL)/256, 256>>>(W_in, whi, wlo, 2*D_INNER*D_MODEL);
        mma_gemm<128,0><<<dim3(2*D_INNER/128, NTOK/128), 256, SMEM_128>>>(
            ahi, alo, whi, wlo, xz, D_MODEL, 2*D_INNER);

        conv_kernel<<<NTOK*D_INNER/256, 256>>>(xz, cw, cb, xm);

        // x_proj split-K + reduce -> xdbl [2048,96]
        gemm_xp<<<dim3(1, NTOK/128, XPS), 256>>>(xm, W_xp, xpp);
        reduce_xp<<<(NTOK*XDBL_W + 255)/256, 256>>>(xpp, xdbl);

        // dt_proj + bias + softplus
        gemm_nt<1><<<dim3(D_INNER/BN, NTOK/BM), 256>>>(
            xdbl, W_dt, dt, NTOK, D_INNER, DT_RANK, XDBL_W, DT_RANK, D_INNER, b_dt);

        // scan -> y as bf16 hi/lo (out_proj A operand)
        scan_kernel<<<(BATCH*D_INNER*D_STATE)/256, 256>>>(dt, xdbl, xm, xz, Al, Dl, ahi, alo);

        // out_proj + residual
        cvt_hilo<<<(D_MODEL*D_INNER)/256, 256>>>(W_out, whi, wlo, D_MODEL*D_INNER);
        mma_gemm<64,2><<<dim3(D_MODEL/128, NTOK/64), 256, SMEM_64>>>(
            ahi, alo, whi, wlo, xcur, D_INNER, D_MODEL);
    }

    ln_kernel<<<NTOK, 256>>>(xcur, (float*)d_out, nullptr, nullptr, ln_g, ln_b);
}